// round 1
// baseline (speedup 1.0000x reference)
#include <cuda_runtime.h>
#include <math.h>

#define D_MODEL 1536
#define S_LEN   4096
#define T_LEN   154
#define N_BC    8
#define N_B     2
#define N_H     24
#define DH      64

// ---------------- scratch (device globals; no allocation allowed) ----------------
__device__ float g_Q [N_BC * S_LEN * D_MODEL];   // 201 MB
__device__ float g_K [N_BC * T_LEN * D_MODEL];   // 7.6 MB
__device__ float g_V [N_BC * T_LEN * D_MODEL];   // 7.6 MB
__device__ float g_AO[N_BC * S_LEN * D_MODEL];   // 201 MB

// ---------------- fp32 SGEMM: Y[M,N] = X[M,K] @ W[N,K]^T + b ----------------
// 128x128 block tile, BK=8, 256 threads, 8x8 per-thread register tile.
__global__ __launch_bounds__(256, 2)
void sgemm_bias(const float* __restrict__ X, const float* __restrict__ W,
                const float* __restrict__ bias, float* __restrict__ Y,
                int M, int N, int K)
{
    __shared__ float As[8][128];
    __shared__ float Bs[8][128];

    const int tid  = threadIdx.x;
    const int bm   = blockIdx.y * 128;
    const int bn   = blockIdx.x * 128;
    const int lrow = tid >> 1;          // 0..127
    const int lc4  = (tid & 1) << 2;    // 0 or 4
    const int tx   = tid & 15;
    const int ty   = tid >> 4;

    float acc[8][8];
    #pragma unroll
    for (int i = 0; i < 8; ++i)
        #pragma unroll
        for (int j = 0; j < 8; ++j) acc[i][j] = 0.f;

    const int   xrow = bm + lrow;
    const bool  xok  = (xrow < M);
    const float* Xp  = X + (size_t)(xok ? xrow : 0) * K + lc4;
    const float* Wp  = W + (size_t)(bn + lrow) * K + lc4;   // N is always a multiple of 128

    for (int k0 = 0; k0 < K; k0 += 8) {
        float4 xa = xok ? *(const float4*)(Xp + k0) : make_float4(0.f, 0.f, 0.f, 0.f);
        float4 wb = *(const float4*)(Wp + k0);
        As[lc4 + 0][lrow] = xa.x; As[lc4 + 1][lrow] = xa.y;
        As[lc4 + 2][lrow] = xa.z; As[lc4 + 3][lrow] = xa.w;
        Bs[lc4 + 0][lrow] = wb.x; Bs[lc4 + 1][lrow] = wb.y;
        Bs[lc4 + 2][lrow] = wb.z; Bs[lc4 + 3][lrow] = wb.w;
        __syncthreads();

        #pragma unroll
        for (int kk = 0; kk < 8; ++kk) {
            float rm[8], rn[8];
            *(float4*)&rm[0] = *(const float4*)&As[kk][ty * 8];
            *(float4*)&rm[4] = *(const float4*)&As[kk][ty * 8 + 4];
            *(float4*)&rn[0] = *(const float4*)&Bs[kk][tx * 8];
            *(float4*)&rn[4] = *(const float4*)&Bs[kk][tx * 8 + 4];
            #pragma unroll
            for (int i = 0; i < 8; ++i)
                #pragma unroll
                for (int j = 0; j < 8; ++j)
                    acc[i][j] = fmaf(rm[i], rn[j], acc[i][j]);
        }
        __syncthreads();
    }

    #pragma unroll
    for (int i = 0; i < 8; ++i) {
        int gm = bm + ty * 8 + i;
        if (gm >= M) continue;
        #pragma unroll
        for (int j = 0; j < 8; j += 4) {
            int gn = bn + tx * 8 + j;
            float4 o;
            o.x = acc[i][j + 0] + bias[gn + 0];
            o.y = acc[i][j + 1] + bias[gn + 1];
            o.z = acc[i][j + 2] + bias[gn + 2];
            o.w = acc[i][j + 3] + bias[gn + 3];
            *(float4*)(Y + (size_t)gm * N + gn) = o;
        }
    }
}

// ---------------- fused decomposing attention ----------------
// Block = (s-tile of 32, head, batch). Processes all 4 components together.
// scores[c,t,s] -> softmax over c per (s,t) -> accumulate per-(s,c) key-sum
// -> out[s,c,d] = (sum_t w*v) / (key-sum + eps).
#define QTS 36   // qT row stride   (qT[c][kk][si])
#define KTS 68   // kv  row stride  (kT[c][kk][tj] / v[c][tj][d])
#define SCS 36   // sc  row stride  (sc[c][t][si])

#define ATTN_SMEM_FLOATS (4*64*QTS + 4*64*KTS + 4*64*SCS + 128)  // 35968
#define ATTN_SMEM_BYTES  (ATTN_SMEM_FLOATS * 4)                  // 143872

__global__ __launch_bounds__(256)
void attn_kernel(const float* __restrict__ Q, const float* __restrict__ K,
                 const float* __restrict__ V, float* __restrict__ O)
{
    extern __shared__ float smem[];
    float* qT = smem;                    // 4*64*QTS
    float* kv = qT + 4 * 64 * QTS;       // 4*64*KTS (K transposed tile, then V natural tile)
    float* sc = kv + 4 * 64 * KTS;       // 4*64*SCS
    float* rs = sc + 4 * 64 * SCS;       // [32][4] key-dimension weight sums

    const int tid = threadIdx.x;
    const int b   = blockIdx.z;
    const int h   = blockIdx.y;
    const int s0  = blockIdx.x * 32;

    if (tid < 128) rs[tid] = 0.f;

    // ---- load Q tile, transposed + pre-scaled by dh^-0.5 = 0.125 ----
    #pragma unroll
    for (int it = 0; it < 8; ++it) {
        int i  = tid + it * 256;             // 4*32*16 float4 loads
        int c  = i >> 9;
        int r  = i & 511;
        int si = r >> 4;
        int k4 = (r & 15) << 2;
        const float* gp = Q + ((size_t)(c * N_B + b) * S_LEN + (s0 + si)) * D_MODEL + h * DH + k4;
        float4 q4 = *(const float4*)gp;
        float* dst = &qT[(c * 64 + k4) * QTS + si];
        dst[0 * QTS] = q4.x * 0.125f;
        dst[1 * QTS] = q4.y * 0.125f;
        dst[2 * QTS] = q4.z * 0.125f;
        dst[3 * QTS] = q4.w * 0.125f;
    }
    __syncthreads();

    // thread tiling shared by score phase and output phase:
    // c = tid/64, 4 s-rows (osg..+3), 8 t-or-d columns (odg..+7)
    const int oc  = tid >> 6;
    const int orr = tid & 63;
    const int osg = (orr >> 3) << 2;
    const int odg = (orr & 7) << 3;

    float acco[4][8];
    #pragma unroll
    for (int i = 0; i < 4; ++i)
        #pragma unroll
        for (int j = 0; j < 8; ++j) acco[i][j] = 0.f;

    for (int t0 = 0; t0 < T_LEN; t0 += 64) {
        const int tcnt = min(64, T_LEN - t0);

        // ---- K tile -> kT[c][kk][tj] ----
        #pragma unroll
        for (int it = 0; it < 16; ++it) {
            int i  = tid + it * 256;
            int c  = i >> 10;
            int r  = i & 1023;
            int tj = r >> 4;
            int k4 = (r & 15) << 2;
            float4 k4v = make_float4(0.f, 0.f, 0.f, 0.f);
            if (tj < tcnt)
                k4v = *(const float4*)(K + ((size_t)(c * N_B + b) * T_LEN + (t0 + tj)) * D_MODEL + h * DH + k4);
            float* dst = &kv[(c * 64 + k4) * KTS + tj];
            dst[0 * KTS] = k4v.x; dst[1 * KTS] = k4v.y;
            dst[2 * KTS] = k4v.z; dst[3 * KTS] = k4v.w;
        }
        __syncthreads();

        // ---- scores: sc[c][t][s] = (q*scale) . k ----
        {
            float a[4][8];
            #pragma unroll
            for (int i = 0; i < 4; ++i)
                #pragma unroll
                for (int j = 0; j < 8; ++j) a[i][j] = 0.f;

            #pragma unroll 4
            for (int kk = 0; kk < 64; ++kk) {
                float4 q4 = *(const float4*)&qT[(oc * 64 + kk) * QTS + osg];
                const float* kp = &kv[(oc * 64 + kk) * KTS + odg];
                float4 kA = *(const float4*)kp;
                float4 kB = *(const float4*)(kp + 4);
                float qv[4] = {q4.x, q4.y, q4.z, q4.w};
                float kw[8] = {kA.x, kA.y, kA.z, kA.w, kB.x, kB.y, kB.z, kB.w};
                #pragma unroll
                for (int i = 0; i < 4; ++i)
                    #pragma unroll
                    for (int j = 0; j < 8; ++j)
                        a[i][j] = fmaf(qv[i], kw[j], a[i][j]);
            }
            #pragma unroll
            for (int j = 0; j < 8; ++j) {
                float4 o = make_float4(a[0][j], a[1][j], a[2][j], a[3][j]);
                *(float4*)&sc[(oc * 64 + odg + j) * SCS + osg] = o;
            }
        }
        __syncthreads();

        // ---- softmax over components (in place) + key-sum accumulation ----
        {
            int s   = tid >> 3;
            int tof = tid & 7;
            float l0 = 0.f, l1 = 0.f, l2 = 0.f, l3 = 0.f;
            for (int t = tof; t < tcnt; t += 8) {
                float x0 = sc[(0 * 64 + t) * SCS + s];
                float x1 = sc[(1 * 64 + t) * SCS + s];
                float x2 = sc[(2 * 64 + t) * SCS + s];
                float x3 = sc[(3 * 64 + t) * SCS + s];
                float m  = fmaxf(fmaxf(x0, x1), fmaxf(x2, x3));
                float e0 = __expf(x0 - m), e1 = __expf(x1 - m);
                float e2 = __expf(x2 - m), e3 = __expf(x3 - m);
                float inv = 1.f / (e0 + e1 + e2 + e3);
                e0 *= inv; e1 *= inv; e2 *= inv; e3 *= inv;
                sc[(0 * 64 + t) * SCS + s] = e0;
                sc[(1 * 64 + t) * SCS + s] = e1;
                sc[(2 * 64 + t) * SCS + s] = e2;
                sc[(3 * 64 + t) * SCS + s] = e3;
                l0 += e0; l1 += e1; l2 += e2; l3 += e3;
            }
            atomicAdd(&rs[s * 4 + 0], l0);
            atomicAdd(&rs[s * 4 + 1], l1);
            atomicAdd(&rs[s * 4 + 2], l2);
            atomicAdd(&rs[s * 4 + 3], l3);
        }

        // ---- V tile -> kv[c][tj][d] (natural; overlaps softmax, no hazard) ----
        #pragma unroll
        for (int it = 0; it < 16; ++it) {
            int i  = tid + it * 256;
            int c  = i >> 10;
            int r  = i & 1023;
            int tj = r >> 4;
            int d4 = (r & 15) << 2;
            float4 v4 = make_float4(0.f, 0.f, 0.f, 0.f);
            if (tj < tcnt)
                v4 = *(const float4*)(V + ((size_t)(c * N_B + b) * T_LEN + (t0 + tj)) * D_MODEL + h * DH + d4);
            *(float4*)&kv[(c * 64 + tj) * KTS + d4] = v4;
        }
        __syncthreads();

        // ---- output accumulation: acco += w[s,c,t] * v[c,t,d] ----
        for (int tj = 0; tj < tcnt; ++tj) {
            float4 w4 = *(const float4*)&sc[(oc * 64 + tj) * SCS + osg];
            const float* vp = &kv[(oc * 64 + tj) * KTS + odg];
            float4 vA = *(const float4*)vp;
            float4 vB = *(const float4*)(vp + 4);
            float wv[4] = {w4.x, w4.y, w4.z, w4.w};
            float vv[8] = {vA.x, vA.y, vA.z, vA.w, vB.x, vB.y, vB.z, vB.w};
            #pragma unroll
            for (int i = 0; i < 4; ++i)
                #pragma unroll
                for (int j = 0; j < 8; ++j)
                    acco[i][j] = fmaf(wv[i], vv[j], acco[i][j]);
        }
        __syncthreads();
    }

    // ---- renormalize over keys and store ----
    #pragma unroll
    for (int i = 0; i < 4; ++i) {
        int s = osg + i;
        float inv = 1.f / (rs[s * 4 + oc] + 1e-8f);
        float* gp = O + ((size_t)(oc * N_B + b) * S_LEN + (s0 + s)) * D_MODEL + h * DH + odg;
        float4 o0, o1;
        o0.x = acco[i][0] * inv; o0.y = acco[i][1] * inv;
        o0.z = acco[i][2] * inv; o0.w = acco[i][3] * inv;
        o1.x = acco[i][4] * inv; o1.y = acco[i][5] * inv;
        o1.z = acco[i][6] * inv; o1.w = acco[i][7] * inv;
        *(float4*)gp       = o0;
        *(float4*)(gp + 4) = o1;
    }
}

// ---------------- launch ----------------
extern "C" void kernel_launch(void* const* d_in, const int* in_sizes, int n_in,
                              void* d_out, int out_size)
{
    const float* HS  = (const float*)d_in[0];
    const float* EHS = (const float*)d_in[1];
    const float* Wq  = (const float*)d_in[2];
    const float* bq  = (const float*)d_in[3];
    const float* Wk  = (const float*)d_in[4];
    const float* bk  = (const float*)d_in[5];
    const float* Wv  = (const float*)d_in[6];
    const float* bv  = (const float*)d_in[7];
    const float* Wo  = (const float*)d_in[8];
    const float* bo  = (const float*)d_in[9];
    float* out = (float*)d_out;

    float *pQ, *pK, *pV, *pAO;
    cudaGetSymbolAddress((void**)&pQ,  g_Q);
    cudaGetSymbolAddress((void**)&pK,  g_K);
    cudaGetSymbolAddress((void**)&pV,  g_V);
    cudaGetSymbolAddress((void**)&pAO, g_AO);

    cudaFuncSetAttribute(attn_kernel, cudaFuncAttributeMaxDynamicSharedMemorySize,
                         ATTN_SMEM_BYTES);

    dim3 blk(256);
    // Q projection: [32768,1536] = HS @ Wq^T + bq
    sgemm_bias<<<dim3(12, 256), blk>>>(HS, Wq, bq, pQ, N_BC * S_LEN, D_MODEL, D_MODEL);
    // K / V projections: [1232,1536]
    sgemm_bias<<<dim3(12, 10), blk>>>(EHS, Wk, bk, pK, N_BC * T_LEN, D_MODEL, D_MODEL);
    sgemm_bias<<<dim3(12, 10), blk>>>(EHS, Wv, bv, pV, N_BC * T_LEN, D_MODEL, D_MODEL);
    // fused component-softmax attention
    attn_kernel<<<dim3(S_LEN / 32, N_H, N_B), blk, ATTN_SMEM_BYTES>>>(pQ, pK, pV, pAO);
    // output projection into d_out
    sgemm_bias<<<dim3(12, 256), blk>>>(pAO, Wo, bo, out, N_BC * S_LEN, D_MODEL, D_MODEL);
}

// round 3
// speedup vs baseline: 1.7810x; 1.7810x over previous
#include <cuda_runtime.h>
#include <cuda_bf16.h>
#include <stdint.h>
#include <math.h>

#define D_MODEL 1536
#define S_LEN   4096
#define T_LEN   154
#define N_BC    8
#define N_B     2
#define N_H     24
#define DH      64

// ---------------- scratch (device globals; no allocation allowed) ----------------
__device__ float g_Q [N_BC * S_LEN * D_MODEL];
__device__ float g_K [N_BC * T_LEN * D_MODEL];
__device__ float g_V [N_BC * T_LEN * D_MODEL];
__device__ float g_AO[N_BC * S_LEN * D_MODEL];

// ================= helpers =================
__device__ __forceinline__ uint32_t smem_u32(const void* p) {
    uint32_t a;
    asm("{ .reg .u64 t; cvta.to.shared.u64 t, %1; cvt.u32.u64 %0, t; }" : "=r"(a) : "l"(p));
    return a;
}
__device__ __forceinline__ void ldm_x4(uint32_t* r, uint32_t addr) {
    asm volatile("ldmatrix.sync.aligned.m8n8.x4.shared.b16 {%0,%1,%2,%3}, [%4];"
        : "=r"(r[0]), "=r"(r[1]), "=r"(r[2]), "=r"(r[3]) : "r"(addr));
}
__device__ __forceinline__ void mma16816(float* d, const uint32_t* a,
                                         uint32_t b0, uint32_t b1) {
    asm volatile(
        "mma.sync.aligned.m16n8k16.row.col.f32.bf16.bf16.f32 "
        "{%0,%1,%2,%3}, {%4,%5,%6,%7}, {%8,%9}, {%0,%1,%2,%3};"
        : "+f"(d[0]), "+f"(d[1]), "+f"(d[2]), "+f"(d[3])
        : "r"(a[0]), "r"(a[1]), "r"(a[2]), "r"(a[3]), "r"(b0), "r"(b1));
}
__device__ __forceinline__ uint32_t pack_hi_lo(float a, float b, float& la, float& lb) {
    __nv_bfloat16 ha = __float2bfloat16(a);
    __nv_bfloat16 hb = __float2bfloat16(b);
    la = a - __bfloat162float(ha);
    lb = b - __bfloat162float(hb);
    __nv_bfloat162 p; p.x = ha; p.y = hb;
    return *(uint32_t*)&p;
}
__device__ __forceinline__ uint32_t pack_lo(float a, float b) {
    __nv_bfloat162 p; p.x = __float2bfloat16(a); p.y = __float2bfloat16(b);
    return *(uint32_t*)&p;
}

// ================= bf16x3 mma.sync GEMM: Y[M,N] = X[M,K] @ W[N,K]^T + b ============
// CTA 128x128, BK=32, 256 threads (8 warps, 4x2), warp tile 32x64.
// SMEM: per stage 4 matrices (Ahi,Alo,Bhi,Blo), each 128 rows x 32 bf16, stride 40.
#define LDA   40
#define MSZ   (128 * LDA)          // bf16 elems per matrix buffer = 5120
#define STAGE (4 * MSZ)            // per stage
#define GEMM_SMEM_BYTES (2 * STAGE * 2)   // 81920 bytes

__global__ __launch_bounds__(256, 1)
void mma_gemm_bias(const float* __restrict__ X, const float* __restrict__ W,
                   const float* __restrict__ bias, float* __restrict__ Y,
                   int M, int N, int K)
{
    extern __shared__ __nv_bfloat16 sm[];
    const uint32_t sbase = smem_u32(sm);

    const int tid  = threadIdx.x;
    const int wid  = tid >> 5;
    const int lane = tid & 31;
    const int bm   = blockIdx.y * 128;
    const int bn   = blockIdx.x * 128;
    const int wm   = wid & 3;        // warp row (32 rows)
    const int wn   = wid >> 2;       // warp col (64 cols)

    // loader indices
    const int lr  = tid >> 3;              // 0..31 base row (x4 iters -> 128)
    const int lc4 = (tid & 7) << 2;        // float col 0..28

    // ldmatrix lane addressing: lanes 0-15 rows r, lanes 16-31 rows r at k+8
    const int xrow = lane & 15;
    const int xk   = (lane >> 4) << 3;

    float acc[2][8][4];
    #pragma unroll
    for (int i = 0; i < 2; ++i)
        #pragma unroll
        for (int j = 0; j < 8; ++j)
            #pragma unroll
            for (int q = 0; q < 4; ++q) acc[i][j][q] = 0.f;

    float4 xa[4], wb[4];

    auto ldg_stage = [&](int k0) {
        #pragma unroll
        for (int t = 0; t < 4; ++t) {
            int row = lr + t * 32;
            int gr  = bm + row;
            xa[t] = (gr < M) ? *(const float4*)(X + (size_t)gr * K + k0 + lc4)
                             : make_float4(0.f, 0.f, 0.f, 0.f);
            wb[t] = *(const float4*)(W + (size_t)(bn + row) * K + k0 + lc4);
        }
    };
    auto sts_stage = [&](int s) {
        __nv_bfloat16* sA_hi = sm + s * STAGE;
        __nv_bfloat16* sA_lo = sA_hi + MSZ;
        __nv_bfloat16* sB_hi = sA_hi + 2 * MSZ;
        __nv_bfloat16* sB_lo = sA_hi + 3 * MSZ;
        #pragma unroll
        for (int t = 0; t < 4; ++t) {
            int row = lr + t * 32;
            int off = row * LDA + lc4;
            float l0, l1, l2, l3;
            uint2 h, l;
            h.x = pack_hi_lo(xa[t].x, xa[t].y, l0, l1);
            h.y = pack_hi_lo(xa[t].z, xa[t].w, l2, l3);
            l.x = pack_lo(l0, l1); l.y = pack_lo(l2, l3);
            *(uint2*)(sA_hi + off) = h;
            *(uint2*)(sA_lo + off) = l;
            h.x = pack_hi_lo(wb[t].x, wb[t].y, l0, l1);
            h.y = pack_hi_lo(wb[t].z, wb[t].w, l2, l3);
            l.x = pack_lo(l0, l1); l.y = pack_lo(l2, l3);
            *(uint2*)(sB_hi + off) = h;
            *(uint2*)(sB_lo + off) = l;
        }
    };

    ldg_stage(0);
    sts_stage(0);
    __syncthreads();

    const int NIT = K / 32;
    for (int it = 0; it < NIT; ++it) {
        if (it + 1 < NIT) ldg_stage((it + 1) * 32);

        const int s = it & 1;
        const uint32_t stg = sbase + s * STAGE * 2;   // byte offset of stage

        #pragma unroll
        for (int kk = 0; kk < 2; ++kk) {
            const int k0 = kk * 16;
            // A fragments (hi & lo) for both m16 halves
            uint32_t afh[2][4], afl[2][4];
            #pragma unroll
            for (int mf = 0; mf < 2; ++mf) {
                uint32_t off = (uint32_t)((wm * 32 + mf * 16 + xrow) * LDA + k0 + xk) * 2;
                ldm_x4(afh[mf], stg + off);                 // Ahi
                ldm_x4(afl[mf], stg + MSZ * 2 + off);       // Alo
            }
            // B in n16 groups; fragment n0-7 = {r0,r2}, n8-15 = {r1,r3}
            #pragma unroll
            for (int nf4 = 0; nf4 < 4; ++nf4) {
                uint32_t off = (uint32_t)((wn * 64 + nf4 * 16 + xrow) * LDA + k0 + xk) * 2;
                uint32_t bh[4], bl[4];
                ldm_x4(bh, stg + 2 * MSZ * 2 + off);        // Bhi
                ldm_x4(bl, stg + 3 * MSZ * 2 + off);        // Blo
                #pragma unroll
                for (int mf = 0; mf < 2; ++mf) {
                    float* d0 = acc[mf][nf4 * 2];
                    float* d1 = acc[mf][nf4 * 2 + 1];
                    mma16816(d0, afh[mf], bh[0], bh[2]);
                    mma16816(d0, afh[mf], bl[0], bl[2]);
                    mma16816(d0, afl[mf], bh[0], bh[2]);
                    mma16816(d1, afh[mf], bh[1], bh[3]);
                    mma16816(d1, afh[mf], bl[1], bl[3]);
                    mma16816(d1, afl[mf], bh[1], bh[3]);
                }
            }
        }

        if (it + 1 < NIT) {
            __syncthreads();
            sts_stage((it + 1) & 1);
            __syncthreads();
        }
    }

    // ---- epilogue ----
    const int g  = lane >> 2;
    const int t2 = (lane & 3) << 1;
    #pragma unroll
    for (int mf = 0; mf < 2; ++mf) {
        int r0 = bm + wm * 32 + mf * 16 + g;
        #pragma unroll
        for (int nf = 0; nf < 8; ++nf) {
            int col = bn + wn * 64 + nf * 8 + t2;
            float b0 = bias[col], b1 = bias[col + 1];
            if (r0 < M) {
                float2 v = make_float2(acc[mf][nf][0] + b0, acc[mf][nf][1] + b1);
                *(float2*)(Y + (size_t)r0 * N + col) = v;
            }
            if (r0 + 8 < M) {
                float2 v = make_float2(acc[mf][nf][2] + b0, acc[mf][nf][3] + b1);
                *(float2*)(Y + (size_t)(r0 + 8) * N + col) = v;
            }
        }
    }
}

// ---------------- fused decomposing attention (unchanged, passing) ----------------
#define QTS 36
#define KTS 68
#define SCS 36
#define ATTN_SMEM_FLOATS (4*64*QTS + 4*64*KTS + 4*64*SCS + 128)
#define ATTN_SMEM_BYTES  (ATTN_SMEM_FLOATS * 4)

__global__ __launch_bounds__(256)
void attn_kernel(const float* __restrict__ Q, const float* __restrict__ K,
                 const float* __restrict__ V, float* __restrict__ O)
{
    extern __shared__ float smemf[];
    float* qT = smemf;
    float* kv = qT + 4 * 64 * QTS;
    float* sc = kv + 4 * 64 * KTS;
    float* rs = sc + 4 * 64 * SCS;

    const int tid = threadIdx.x;
    const int b   = blockIdx.z;
    const int h   = blockIdx.y;
    const int s0  = blockIdx.x * 32;

    if (tid < 128) rs[tid] = 0.f;

    #pragma unroll
    for (int it = 0; it < 8; ++it) {
        int i  = tid + it * 256;
        int c  = i >> 9;
        int r  = i & 511;
        int si = r >> 4;
        int k4 = (r & 15) << 2;
        const float* gp = Q + ((size_t)(c * N_B + b) * S_LEN + (s0 + si)) * D_MODEL + h * DH + k4;
        float4 q4 = *(const float4*)gp;
        float* dst = &qT[(c * 64 + k4) * QTS + si];
        dst[0 * QTS] = q4.x * 0.125f;
        dst[1 * QTS] = q4.y * 0.125f;
        dst[2 * QTS] = q4.z * 0.125f;
        dst[3 * QTS] = q4.w * 0.125f;
    }
    __syncthreads();

    const int oc  = tid >> 6;
    const int orr = tid & 63;
    const int osg = (orr >> 3) << 2;
    const int odg = (orr & 7) << 3;

    float acco[4][8];
    #pragma unroll
    for (int i = 0; i < 4; ++i)
        #pragma unroll
        for (int j = 0; j < 8; ++j) acco[i][j] = 0.f;

    for (int t0 = 0; t0 < T_LEN; t0 += 64) {
        const int tcnt = min(64, T_LEN - t0);

        #pragma unroll
        for (int it = 0; it < 16; ++it) {
            int i  = tid + it * 256;
            int c  = i >> 10;
            int r  = i & 1023;
            int tj = r >> 4;
            int k4 = (r & 15) << 2;
            float4 k4v = make_float4(0.f, 0.f, 0.f, 0.f);
            if (tj < tcnt)
                k4v = *(const float4*)(K + ((size_t)(c * N_B + b) * T_LEN + (t0 + tj)) * D_MODEL + h * DH + k4);
            float* dst = &kv[(c * 64 + k4) * KTS + tj];
            dst[0 * KTS] = k4v.x; dst[1 * KTS] = k4v.y;
            dst[2 * KTS] = k4v.z; dst[3 * KTS] = k4v.w;
        }
        __syncthreads();

        {
            float a[4][8];
            #pragma unroll
            for (int i = 0; i < 4; ++i)
                #pragma unroll
                for (int j = 0; j < 8; ++j) a[i][j] = 0.f;

            #pragma unroll 4
            for (int kk = 0; kk < 64; ++kk) {
                float4 q4 = *(const float4*)&qT[(oc * 64 + kk) * QTS + osg];
                const float* kp = &kv[(oc * 64 + kk) * KTS + odg];
                float4 kA = *(const float4*)kp;
                float4 kB = *(const float4*)(kp + 4);
                float qv[4] = {q4.x, q4.y, q4.z, q4.w};
                float kw[8] = {kA.x, kA.y, kA.z, kA.w, kB.x, kB.y, kB.z, kB.w};
                #pragma unroll
                for (int i = 0; i < 4; ++i)
                    #pragma unroll
                    for (int j = 0; j < 8; ++j)
                        a[i][j] = fmaf(qv[i], kw[j], a[i][j]);
            }
            #pragma unroll
            for (int j = 0; j < 8; ++j) {
                float4 o = make_float4(a[0][j], a[1][j], a[2][j], a[3][j]);
                *(float4*)&sc[(oc * 64 + odg + j) * SCS + osg] = o;
            }
        }
        __syncthreads();

        {
            int s   = tid >> 3;
            int tof = tid & 7;
            float l0 = 0.f, l1 = 0.f, l2 = 0.f, l3 = 0.f;
            for (int t = tof; t < tcnt; t += 8) {
                float x0 = sc[(0 * 64 + t) * SCS + s];
                float x1 = sc[(1 * 64 + t) * SCS + s];
                float x2 = sc[(2 * 64 + t) * SCS + s];
                float x3 = sc[(3 * 64 + t) * SCS + s];
                float m  = fmaxf(fmaxf(x0, x1), fmaxf(x2, x3));
                float e0 = __expf(x0 - m), e1 = __expf(x1 - m);
                float e2 = __expf(x2 - m), e3 = __expf(x3 - m);
                float inv = 1.f / (e0 + e1 + e2 + e3);
                e0 *= inv; e1 *= inv; e2 *= inv; e3 *= inv;
                sc[(0 * 64 + t) * SCS + s] = e0;
                sc[(1 * 64 + t) * SCS + s] = e1;
                sc[(2 * 64 + t) * SCS + s] = e2;
                sc[(3 * 64 + t) * SCS + s] = e3;
                l0 += e0; l1 += e1; l2 += e2; l3 += e3;
            }
            atomicAdd(&rs[s * 4 + 0], l0);
            atomicAdd(&rs[s * 4 + 1], l1);
            atomicAdd(&rs[s * 4 + 2], l2);
            atomicAdd(&rs[s * 4 + 3], l3);
        }

        #pragma unroll
        for (int it = 0; it < 16; ++it) {
            int i  = tid + it * 256;
            int c  = i >> 10;
            int r  = i & 1023;
            int tj = r >> 4;
            int d4 = (r & 15) << 2;
            float4 v4 = make_float4(0.f, 0.f, 0.f, 0.f);
            if (tj < tcnt)
                v4 = *(const float4*)(V + ((size_t)(c * N_B + b) * T_LEN + (t0 + tj)) * D_MODEL + h * DH + d4);
            *(float4*)&kv[(c * 64 + tj) * KTS + d4] = v4;
        }
        __syncthreads();

        for (int tj = 0; tj < tcnt; ++tj) {
            float4 w4 = *(const float4*)&sc[(oc * 64 + tj) * SCS + osg];
            const float* vp = &kv[(oc * 64 + tj) * KTS + odg];
            float4 vA = *(const float4*)vp;
            float4 vB = *(const float4*)(vp + 4);
            float wv[4] = {w4.x, w4.y, w4.z, w4.w};
            float vv[8] = {vA.x, vA.y, vA.z, vA.w, vB.x, vB.y, vB.z, vB.w};
            #pragma unroll
            for (int i = 0; i < 4; ++i)
                #pragma unroll
                for (int j = 0; j < 8; ++j)
                    acco[i][j] = fmaf(wv[i], vv[j], acco[i][j]);
        }
        __syncthreads();
    }

    #pragma unroll
    for (int i = 0; i < 4; ++i) {
        int s = osg + i;
        float inv = 1.f / (rs[s * 4 + oc] + 1e-8f);
        float* gp = O + ((size_t)(oc * N_B + b) * S_LEN + (s0 + s)) * D_MODEL + h * DH + odg;
        float4 o0, o1;
        o0.x = acco[i][0] * inv; o0.y = acco[i][1] * inv;
        o0.z = acco[i][2] * inv; o0.w = acco[i][3] * inv;
        o1.x = acco[i][4] * inv; o1.y = acco[i][5] * inv;
        o1.z = acco[i][6] * inv; o1.w = acco[i][7] * inv;
        *(float4*)gp       = o0;
        *(float4*)(gp + 4) = o1;
    }
}

// ---------------- launch ----------------
extern "C" void kernel_launch(void* const* d_in, const int* in_sizes, int n_in,
                              void* d_out, int out_size)
{
    const float* HS  = (const float*)d_in[0];
    const float* EHS = (const float*)d_in[1];
    const float* Wq  = (const float*)d_in[2];
    const float* bq  = (const float*)d_in[3];
    const float* Wk  = (const float*)d_in[4];
    const float* bk  = (const float*)d_in[5];
    const float* Wv  = (const float*)d_in[6];
    const float* bv  = (const float*)d_in[7];
    const float* Wo  = (const float*)d_in[8];
    const float* bo  = (const float*)d_in[9];
    float* out = (float*)d_out;

    float *pQ, *pK, *pV, *pAO;
    cudaGetSymbolAddress((void**)&pQ,  g_Q);
    cudaGetSymbolAddress((void**)&pK,  g_K);
    cudaGetSymbolAddress((void**)&pV,  g_V);
    cudaGetSymbolAddress((void**)&pAO, g_AO);

    cudaFuncSetAttribute(mma_gemm_bias, cudaFuncAttributeMaxDynamicSharedMemorySize,
                         GEMM_SMEM_BYTES);
    cudaFuncSetAttribute(attn_kernel, cudaFuncAttributeMaxDynamicSharedMemorySize,
                         ATTN_SMEM_BYTES);

    dim3 blk(256);
    // Q projection: [32768,1536]
    mma_gemm_bias<<<dim3(12, 256), blk, GEMM_SMEM_BYTES>>>(HS, Wq, bq, pQ, N_BC * S_LEN, D_MODEL, D_MODEL);
    // K / V projections: [1232,1536]
    mma_gemm_bias<<<dim3(12, 10), blk, GEMM_SMEM_BYTES>>>(EHS, Wk, bk, pK, N_BC * T_LEN, D_MODEL, D_MODEL);
    mma_gemm_bias<<<dim3(12, 10), blk, GEMM_SMEM_BYTES>>>(EHS, Wv, bv, pV, N_BC * T_LEN, D_MODEL, D_MODEL);
    // fused component-softmax attention
    attn_kernel<<<dim3(S_LEN / 32, N_H, N_B), blk, ATTN_SMEM_BYTES>>>(pQ, pK, pV, pAO);
    // output projection into d_out
    mma_gemm_bias<<<dim3(12, 256), blk, GEMM_SMEM_BYTES>>>(pAO, Wo, bo, out, N_BC * S_LEN, D_MODEL, D_MODEL);
}

// round 4
// speedup vs baseline: 3.0417x; 1.7079x over previous
#include <cuda_runtime.h>
#include <cuda_fp16.h>
#include <stdint.h>
#include <math.h>

#define D_MODEL 1536
#define S_LEN   4096
#define T_LEN   154
#define N_BC    8
#define N_B     2
#define N_H     24
#define DH      64

// ---------------- scratch (device globals; no allocation allowed) ----------------
__device__ float  g_Q  [N_BC * S_LEN * D_MODEL];   // fp32 Q
__device__ float  g_K  [N_BC * T_LEN * D_MODEL];
__device__ float  g_V  [N_BC * T_LEN * D_MODEL];
__device__ __half g_HSh [N_BC * S_LEN * D_MODEL];  // fp16 copies
__device__ __half g_EHSh[N_BC * T_LEN * D_MODEL];
__device__ __half g_AOh [N_BC * S_LEN * D_MODEL];
__device__ __half g_Wqh[D_MODEL * D_MODEL];
__device__ __half g_Wkh[D_MODEL * D_MODEL];
__device__ __half g_Wvh[D_MODEL * D_MODEL];
__device__ __half g_Woh[D_MODEL * D_MODEL];

// ================= helpers =================
__device__ __forceinline__ uint32_t smem_u32(const void* p) {
    uint32_t a;
    asm("{ .reg .u64 t; cvta.to.shared.u64 t, %1; cvt.u32.u64 %0, t; }" : "=r"(a) : "l"(p));
    return a;
}
__device__ __forceinline__ void ldm_x4(uint32_t* r, uint32_t addr) {
    asm volatile("ldmatrix.sync.aligned.m8n8.x4.shared.b16 {%0,%1,%2,%3}, [%4];"
        : "=r"(r[0]), "=r"(r[1]), "=r"(r[2]), "=r"(r[3]) : "r"(addr));
}
__device__ __forceinline__ void mma16816h(float* d, const uint32_t* a,
                                          uint32_t b0, uint32_t b1) {
    asm volatile(
        "mma.sync.aligned.m16n8k16.row.col.f32.f16.f16.f32 "
        "{%0,%1,%2,%3}, {%4,%5,%6,%7}, {%8,%9}, {%0,%1,%2,%3};"
        : "+f"(d[0]), "+f"(d[1]), "+f"(d[2]), "+f"(d[3])
        : "r"(a[0]), "r"(a[1]), "r"(a[2]), "r"(a[3]), "r"(b0), "r"(b1));
}
__device__ __forceinline__ void cp_async16(uint32_t dst, const void* src) {
    asm volatile("cp.async.cg.shared.global [%0], [%1], 16;" :: "r"(dst), "l"(src));
}
#define CP_COMMIT() asm volatile("cp.async.commit_group;" ::: "memory")
#define CP_WAIT(n)  asm volatile("cp.async.wait_group %0;" :: "n"(n) : "memory")

// ================= fp32 -> fp16 convert =================
__global__ void f2h_kernel(const float* __restrict__ x, __half* __restrict__ y, int n4)
{
    int i = blockIdx.x * blockDim.x + threadIdx.x;
    if (i < n4) {
        float4 v = ((const float4*)x)[i];
        __half2* yp = (__half2*)y + i * 2;
        yp[0] = __floats2half2_rn(v.x, v.y);
        yp[1] = __floats2half2_rn(v.z, v.w);
    }
}

// ================= fp16 HGEMM: Y[M,N] = A[M,K] @ B[N,K]^T + bias ====================
// CTA 128x128, BK=32, 256 threads (8 warps 4x2), warp tile 32x64, 3-stage cp.async.
#define LDA    40                    // halfs per smem row (80B, ldmatrix conflict-free)
#define ASTG   (128 * LDA)           // halfs per matrix buffer
#define STG2   (2 * ASTG)            // halfs per stage (A + B)
#define NSTAGE 3
#define GEMM_SMEM_BYTES (NSTAGE * STG2 * 2)   // 61440

__global__ __launch_bounds__(256, 2)
void hgemm_bias(const __half* __restrict__ A, const __half* __restrict__ B,
                const float* __restrict__ bias, float* __restrict__ Y,
                int M, int N, int K)
{
    extern __shared__ __half sm[];
    const uint32_t sbase = smem_u32(sm);
    const int tid  = threadIdx.x;
    const int wid  = tid >> 5;
    const int lane = tid & 31;
    const int bm   = blockIdx.y * 128;
    const int bn   = blockIdx.x * 128;
    const int wm   = wid & 3;
    const int wn   = wid >> 2;
    const int xrow = lane & 15;
    const int xk   = (lane >> 4) << 3;

    // loader: thread handles 2 chunks of 16B per matrix per stage
    const int crow = tid >> 2;              // 0..63
    const int ccol = (tid & 3) << 3;        // half col 0,8,16,24
    const int ar0 = min(bm + crow,      M - 1);
    const int ar1 = min(bm + crow + 64, M - 1);
    const __half* a0 = A + (size_t)ar0 * K + ccol;
    const __half* a1 = A + (size_t)ar1 * K + ccol;
    const __half* b0 = B + (size_t)(bn + crow) * K + ccol;
    const __half* b1 = B + (size_t)(bn + crow + 64) * K + ccol;
    const uint32_t so0 = (uint32_t)(crow * LDA + ccol) * 2;
    const uint32_t so1 = (uint32_t)((crow + 64) * LDA + ccol) * 2;

    float acc[2][8][4];
    #pragma unroll
    for (int i = 0; i < 2; ++i)
        #pragma unroll
        for (int j = 0; j < 8; ++j)
            #pragma unroll
            for (int q = 0; q < 4; ++q) acc[i][j][q] = 0.f;

    const int NIT = K / 32;

    auto issue = [&](int it) {
        const int s  = it % NSTAGE;
        const int k0 = it * 32;
        uint32_t sa = sbase + (uint32_t)s * STG2 * 2;
        uint32_t sb = sa + ASTG * 2;
        cp_async16(sa + so0, a0 + k0);
        cp_async16(sa + so1, a1 + k0);
        cp_async16(sb + so0, b0 + k0);
        cp_async16(sb + so1, b1 + k0);
    };

    issue(0); CP_COMMIT();
    issue(1); CP_COMMIT();

    for (int it = 0; it < NIT; ++it) {
        if (it == NIT - 1) { CP_WAIT(0); } else { CP_WAIT(1); }
        __syncthreads();
        if (it + 2 < NIT) { issue(it + 2); CP_COMMIT(); }

        const int s = it % NSTAGE;
        const uint32_t sa = sbase + (uint32_t)s * STG2 * 2;
        const uint32_t sb = sa + ASTG * 2;

        #pragma unroll
        for (int kk = 0; kk < 2; ++kk) {
            const int k0 = kk * 16;
            uint32_t af[2][4];
            #pragma unroll
            for (int mf = 0; mf < 2; ++mf)
                ldm_x4(af[mf], sa + (uint32_t)((wm * 32 + mf * 16 + xrow) * LDA + k0 + xk) * 2);
            #pragma unroll
            for (int nf4 = 0; nf4 < 4; ++nf4) {
                uint32_t bf[4];
                ldm_x4(bf, sb + (uint32_t)((wn * 64 + nf4 * 16 + xrow) * LDA + k0 + xk) * 2);
                #pragma unroll
                for (int mf = 0; mf < 2; ++mf) {
                    mma16816h(acc[mf][nf4 * 2],     af[mf], bf[0], bf[2]);
                    mma16816h(acc[mf][nf4 * 2 + 1], af[mf], bf[1], bf[3]);
                }
            }
        }
    }
    __syncthreads();

    // ---- epilogue ----
    const int g  = lane >> 2;
    const int t2 = (lane & 3) << 1;
    #pragma unroll
    for (int mf = 0; mf < 2; ++mf) {
        int r0 = bm + wm * 32 + mf * 16 + g;
        #pragma unroll
        for (int nf = 0; nf < 8; ++nf) {
            int col = bn + wn * 64 + nf * 8 + t2;
            float bv0 = bias[col], bv1 = bias[col + 1];
            if (r0 < M) {
                float2 v = make_float2(acc[mf][nf][0] + bv0, acc[mf][nf][1] + bv1);
                *(float2*)(Y + (size_t)r0 * N + col) = v;
            }
            if (r0 + 8 < M) {
                float2 v = make_float2(acc[mf][nf][2] + bv0, acc[mf][nf][3] + bv1);
                *(float2*)(Y + (size_t)(r0 + 8) * N + col) = v;
            }
        }
    }
}

// ---------------- fused decomposing attention (fp32 core, fp16 output) ----------------
#define QTS 36
#define KTS 68
#define SCS 36
#define ATTN_SMEM_FLOATS (4*64*QTS + 4*64*KTS + 4*64*SCS + 128)
#define ATTN_SMEM_BYTES  (ATTN_SMEM_FLOATS * 4)

__global__ __launch_bounds__(256)
void attn_kernel(const float* __restrict__ Q, const float* __restrict__ K,
                 const float* __restrict__ V, __half* __restrict__ O)
{
    extern __shared__ float smemf[];
    float* qT = smemf;
    float* kv = qT + 4 * 64 * QTS;
    float* sc = kv + 4 * 64 * KTS;
    float* rs = sc + 4 * 64 * SCS;

    const int tid = threadIdx.x;
    const int b   = blockIdx.z;
    const int h   = blockIdx.y;
    const int s0  = blockIdx.x * 32;

    if (tid < 128) rs[tid] = 0.f;

    #pragma unroll
    for (int it = 0; it < 8; ++it) {
        int i  = tid + it * 256;
        int c  = i >> 9;
        int r  = i & 511;
        int si = r >> 4;
        int k4 = (r & 15) << 2;
        const float* gp = Q + ((size_t)(c * N_B + b) * S_LEN + (s0 + si)) * D_MODEL + h * DH + k4;
        float4 q4 = *(const float4*)gp;
        float* dst = &qT[(c * 64 + k4) * QTS + si];
        dst[0 * QTS] = q4.x * 0.125f;
        dst[1 * QTS] = q4.y * 0.125f;
        dst[2 * QTS] = q4.z * 0.125f;
        dst[3 * QTS] = q4.w * 0.125f;
    }
    __syncthreads();

    const int oc  = tid >> 6;
    const int orr = tid & 63;
    const int osg = (orr >> 3) << 2;
    const int odg = (orr & 7) << 3;

    float acco[4][8];
    #pragma unroll
    for (int i = 0; i < 4; ++i)
        #pragma unroll
        for (int j = 0; j < 8; ++j) acco[i][j] = 0.f;

    for (int t0 = 0; t0 < T_LEN; t0 += 64) {
        const int tcnt = min(64, T_LEN - t0);

        #pragma unroll
        for (int it = 0; it < 16; ++it) {
            int i  = tid + it * 256;
            int c  = i >> 10;
            int r  = i & 1023;
            int tj = r >> 4;
            int k4 = (r & 15) << 2;
            float4 k4v = make_float4(0.f, 0.f, 0.f, 0.f);
            if (tj < tcnt)
                k4v = *(const float4*)(K + ((size_t)(c * N_B + b) * T_LEN + (t0 + tj)) * D_MODEL + h * DH + k4);
            float* dst = &kv[(c * 64 + k4) * KTS + tj];
            dst[0 * KTS] = k4v.x; dst[1 * KTS] = k4v.y;
            dst[2 * KTS] = k4v.z; dst[3 * KTS] = k4v.w;
        }
        __syncthreads();

        {
            float a[4][8];
            #pragma unroll
            for (int i = 0; i < 4; ++i)
                #pragma unroll
                for (int j = 0; j < 8; ++j) a[i][j] = 0.f;

            #pragma unroll 4
            for (int kk = 0; kk < 64; ++kk) {
                float4 q4 = *(const float4*)&qT[(oc * 64 + kk) * QTS + osg];
                const float* kp = &kv[(oc * 64 + kk) * KTS + odg];
                float4 kA = *(const float4*)kp;
                float4 kB = *(const float4*)(kp + 4);
                float qv[4] = {q4.x, q4.y, q4.z, q4.w};
                float kw[8] = {kA.x, kA.y, kA.z, kA.w, kB.x, kB.y, kB.z, kB.w};
                #pragma unroll
                for (int i = 0; i < 4; ++i)
                    #pragma unroll
                    for (int j = 0; j < 8; ++j)
                        a[i][j] = fmaf(qv[i], kw[j], a[i][j]);
            }
            #pragma unroll
            for (int j = 0; j < 8; ++j) {
                float4 o = make_float4(a[0][j], a[1][j], a[2][j], a[3][j]);
                *(float4*)&sc[(oc * 64 + odg + j) * SCS + osg] = o;
            }
        }
        __syncthreads();

        {
            int s   = tid >> 3;
            int tof = tid & 7;
            float l0 = 0.f, l1 = 0.f, l2 = 0.f, l3 = 0.f;
            for (int t = tof; t < tcnt; t += 8) {
                float x0 = sc[(0 * 64 + t) * SCS + s];
                float x1 = sc[(1 * 64 + t) * SCS + s];
                float x2 = sc[(2 * 64 + t) * SCS + s];
                float x3 = sc[(3 * 64 + t) * SCS + s];
                float m  = fmaxf(fmaxf(x0, x1), fmaxf(x2, x3));
                float e0 = __expf(x0 - m), e1 = __expf(x1 - m);
                float e2 = __expf(x2 - m), e3 = __expf(x3 - m);
                float inv = 1.f / (e0 + e1 + e2 + e3);
                e0 *= inv; e1 *= inv; e2 *= inv; e3 *= inv;
                sc[(0 * 64 + t) * SCS + s] = e0;
                sc[(1 * 64 + t) * SCS + s] = e1;
                sc[(2 * 64 + t) * SCS + s] = e2;
                sc[(3 * 64 + t) * SCS + s] = e3;
                l0 += e0; l1 += e1; l2 += e2; l3 += e3;
            }
            atomicAdd(&rs[s * 4 + 0], l0);
            atomicAdd(&rs[s * 4 + 1], l1);
            atomicAdd(&rs[s * 4 + 2], l2);
            atomicAdd(&rs[s * 4 + 3], l3);
        }

        #pragma unroll
        for (int it = 0; it < 16; ++it) {
            int i  = tid + it * 256;
            int c  = i >> 10;
            int r  = i & 1023;
            int tj = r >> 4;
            int d4 = (r & 15) << 2;
            float4 v4 = make_float4(0.f, 0.f, 0.f, 0.f);
            if (tj < tcnt)
                v4 = *(const float4*)(V + ((size_t)(c * N_B + b) * T_LEN + (t0 + tj)) * D_MODEL + h * DH + d4);
            *(float4*)&kv[(c * 64 + tj) * KTS + d4] = v4;
        }
        __syncthreads();

        for (int tj = 0; tj < tcnt; ++tj) {
            float4 w4 = *(const float4*)&sc[(oc * 64 + tj) * SCS + osg];
            const float* vp = &kv[(oc * 64 + tj) * KTS + odg];
            float4 vA = *(const float4*)vp;
            float4 vB = *(const float4*)(vp + 4);
            float wv[4] = {w4.x, w4.y, w4.z, w4.w};
            float vv[8] = {vA.x, vA.y, vA.z, vA.w, vB.x, vB.y, vB.z, vB.w};
            #pragma unroll
            for (int i = 0; i < 4; ++i)
                #pragma unroll
                for (int j = 0; j < 8; ++j)
                    acco[i][j] = fmaf(wv[i], vv[j], acco[i][j]);
        }
        __syncthreads();
    }

    #pragma unroll
    for (int i = 0; i < 4; ++i) {
        int s = osg + i;
        float inv = 1.f / (rs[s * 4 + oc] + 1e-8f);
        __half* gp = O + ((size_t)(oc * N_B + b) * S_LEN + (s0 + s)) * D_MODEL + h * DH + odg;
        __half2 h0 = __floats2half2_rn(acco[i][0] * inv, acco[i][1] * inv);
        __half2 h1 = __floats2half2_rn(acco[i][2] * inv, acco[i][3] * inv);
        __half2 h2 = __floats2half2_rn(acco[i][4] * inv, acco[i][5] * inv);
        __half2 h3 = __floats2half2_rn(acco[i][6] * inv, acco[i][7] * inv);
        uint4 pk;
        pk.x = *(uint32_t*)&h0; pk.y = *(uint32_t*)&h1;
        pk.z = *(uint32_t*)&h2; pk.w = *(uint32_t*)&h3;
        *(uint4*)gp = pk;
    }
}

// ---------------- launch ----------------
extern "C" void kernel_launch(void* const* d_in, const int* in_sizes, int n_in,
                              void* d_out, int out_size)
{
    const float* HS  = (const float*)d_in[0];
    const float* EHS = (const float*)d_in[1];
    const float* Wq  = (const float*)d_in[2];
    const float* bq  = (const float*)d_in[3];
    const float* Wk  = (const float*)d_in[4];
    const float* bk  = (const float*)d_in[5];
    const float* Wv  = (const float*)d_in[6];
    const float* bv  = (const float*)d_in[7];
    const float* Wo  = (const float*)d_in[8];
    const float* bo  = (const float*)d_in[9];
    float* out = (float*)d_out;

    float *pQ, *pK, *pV;
    __half *pHSh, *pEHSh, *pAOh, *pWqh, *pWkh, *pWvh, *pWoh;
    cudaGetSymbolAddress((void**)&pQ,   g_Q);
    cudaGetSymbolAddress((void**)&pK,   g_K);
    cudaGetSymbolAddress((void**)&pV,   g_V);
    cudaGetSymbolAddress((void**)&pHSh, g_HSh);
    cudaGetSymbolAddress((void**)&pEHSh,g_EHSh);
    cudaGetSymbolAddress((void**)&pAOh, g_AOh);
    cudaGetSymbolAddress((void**)&pWqh, g_Wqh);
    cudaGetSymbolAddress((void**)&pWkh, g_Wkh);
    cudaGetSymbolAddress((void**)&pWvh, g_Wvh);
    cudaGetSymbolAddress((void**)&pWoh, g_Woh);

    cudaFuncSetAttribute(hgemm_bias, cudaFuncAttributeMaxDynamicSharedMemorySize,
                         GEMM_SMEM_BYTES);
    cudaFuncSetAttribute(attn_kernel, cudaFuncAttributeMaxDynamicSharedMemorySize,
                         ATTN_SMEM_BYTES);

    dim3 blk(256);
    const int nHS = N_BC * S_LEN * D_MODEL / 4;
    const int nEH = N_BC * T_LEN * D_MODEL / 4;
    const int nW  = D_MODEL * D_MODEL / 4;
    f2h_kernel<<<(nHS + 255) / 256, blk>>>(HS,  pHSh,  nHS);
    f2h_kernel<<<(nEH + 255) / 256, blk>>>(EHS, pEHSh, nEH);
    f2h_kernel<<<(nW  + 255) / 256, blk>>>(Wq,  pWqh,  nW);
    f2h_kernel<<<(nW  + 255) / 256, blk>>>(Wk,  pWkh,  nW);
    f2h_kernel<<<(nW  + 255) / 256, blk>>>(Wv,  pWvh,  nW);
    f2h_kernel<<<(nW  + 255) / 256, blk>>>(Wo,  pWoh,  nW);

    // projections
    hgemm_bias<<<dim3(12, 256), blk, GEMM_SMEM_BYTES>>>(pHSh,  pWqh, bq, pQ, N_BC * S_LEN, D_MODEL, D_MODEL);
    hgemm_bias<<<dim3(12, 10),  blk, GEMM_SMEM_BYTES>>>(pEHSh, pWkh, bk, pK, N_BC * T_LEN, D_MODEL, D_MODEL);
    hgemm_bias<<<dim3(12, 10),  blk, GEMM_SMEM_BYTES>>>(pEHSh, pWvh, bv, pV, N_BC * T_LEN, D_MODEL, D_MODEL);
    // fused component-softmax attention (fp16 output)
    attn_kernel<<<dim3(S_LEN / 32, N_H, N_B), blk, ATTN_SMEM_BYTES>>>(pQ, pK, pV, pAOh);
    // output projection into d_out
    hgemm_bias<<<dim3(12, 256), blk, GEMM_SMEM_BYTES>>>(pAOh, pWoh, bo, out, N_BC * S_LEN, D_MODEL, D_MODEL);
}